// round 1
// baseline (speedup 1.0000x reference)
#include <cuda_runtime.h>
#include <cuda_bf16.h>

// Problem constants (fixed by the reference setup):
//   H=W=128, B=16, KS=21, grid centers at (4i+2, 4j+2), i,j in [0,32)
//   deformation = depthwise SAME conv of sparse beta image with 21x21 gaussian
//   out[b, r*128+c] = sum_{i,j} alphas[i*32+j] *
//                     exp(-((x-(4i+2))^2 + (y-(4j+2))^2) / 50)
//   where x = r - def_row(b,r,c), y = c - def_col(b,r,c)
//
// Separable + truncated to a 13x13 center window (excluded weights < 1.4e-6).

#define TPB 256

__global__ __launch_bounds__(TPB) void rbf_deform_kernel(
    const float* __restrict__ betas,   // (16, 1024, 2)
    const float* __restrict__ alphas,  // (1024,)
    const float* __restrict__ kern,    // (21, 21)
    float* __restrict__ out)           // (16, 16384)
{
    // Zero-padded shared tables (padding absorbs all boundary handling):
    __shared__ float sA[44 * 44];        // alphas as 32x32, pad 6 each side
    __shared__ float sB[2 * 38 * 38];    // betas[b] per channel, pad 2/4
    __shared__ float sK[24 * 24];        // 21x21 kernel, pad 3 low / ~0 high

    const int b   = blockIdx.y;
    const int r0  = (blockIdx.x >> 3) << 4;   // 8x8 tiles of 16x16 pixels
    const int c0  = (blockIdx.x & 7)  << 4;
    const int tid = threadIdx.x;

    // ---- cooperative smem fills (all sources are tiny & L2-resident) ----
    for (int idx = tid; idx < 44 * 44; idx += TPB) {
        const int i = idx / 44 - 6, j = idx % 44 - 6;
        float v = 0.f;
        if ((unsigned)i < 32u && (unsigned)j < 32u) v = alphas[i * 32 + j];
        sA[idx] = v;
    }
    for (int idx = tid; idx < 38 * 38; idx += TPB) {
        const int gi = idx / 38 - 2, gj = idx % 38 - 2;
        float v0 = 0.f, v1 = 0.f;
        if ((unsigned)gi < 32u && (unsigned)gj < 32u) {
            const int m = (b * 1024 + gi * 32 + gj) * 2;
            v0 = betas[m];
            v1 = betas[m + 1];
        }
        sB[idx]           = v0;
        sB[38 * 38 + idx] = v1;
    }
    for (int idx = tid; idx < 24 * 24; idx += TPB) {
        const int u = idx / 24 - 3, v = idx % 24 - 3;   // u = dr+10, v = dc+10
        float w = 0.f;
        if ((unsigned)u < 21u && (unsigned)v < 21u) w = kern[u * 21 + v];
        sK[idx] = w;
    }
    __syncthreads();

    const int r = r0 + (tid >> 4);
    const int c = c0 + (tid & 15);

    // ---- deformation: 6x6 grid window, weights from the provided kernel ----
    // gi0 = ceil((r-10)/4); dr = r-4*gi in [-13,10]; sK pad zeros dr<-10.
    const int gi0 = ((r + 33) >> 2) - 10;
    const int gj0 = ((c + 33) >> 2) - 10;
    float def0 = 0.f, def1 = 0.f;
#pragma unroll
    for (int k = 0; k < 6; ++k) {
        const int gi = gi0 + k;
        const int dr = r - 4 * gi;
        const float* kr = &sK[(dr + 13) * 24 + 13];       // index by dc
        const float* b0 = &sB[(gi + 2) * 38 + 2];         // index by gj
        const float* b1 = b0 + 38 * 38;
        float a0 = 0.f, a1 = 0.f;
#pragma unroll
        for (int l = 0; l < 6; ++l) {
            const int gj = gj0 + l;
            const int dc = c - 4 * gj;
            const float w = kr[dc];
            a0 = fmaf(w, b0[gj], a0);
            a1 = fmaf(w, b1[gj], a1);
        }
        def0 += a0;
        def1 += a1;
    }

    const float x = (float)r - def0;
    const float y = (float)c - def1;

    // ---- separable RBF over a 13x13 center window around the nearest center ----
    int ic = __float2int_rn((x - 2.0f) * 0.25f);
    int jc = __float2int_rn((y - 2.0f) * 0.25f);
    ic = min(max(ic, 0), 31);
    jc = min(max(jc, 0), 31);

    float ex[13], ey[13];
#pragma unroll
    for (int k = 0; k < 13; ++k) {
        const float dxv = x - (float)(4 * (ic - 6 + k) + 2);
        const float dyv = y - (float)(4 * (jc - 6 + k) + 2);
        ex[k] = __expf(dxv * dxv * (-1.0f / 50.0f));
        ey[k] = __expf(dyv * dyv * (-1.0f / 50.0f));
    }

    // out = ex^T * A[window] * ey ; sA padding zeroes out-of-range centers.
    float acc = 0.f;
#pragma unroll
    for (int k = 0; k < 13; ++k) {
        const float* Ar = &sA[(ic + k) * 44 + jc];   // = ((ic-6+k)+6)*44 + (jc-6)+6
        float s = 0.f;
#pragma unroll
        for (int l = 0; l < 13; ++l)
            s = fmaf(Ar[l], ey[l], s);
        acc = fmaf(ex[k], s, acc);
    }

    out[(b << 14) + (r << 7) + c] = acc;
}

extern "C" void kernel_launch(void* const* d_in, const int* in_sizes, int n_in,
                              void* d_out, int out_size) {
    const float* betas  = (const float*)d_in[0];
    const float* alphas = (const float*)d_in[1];
    const float* kern   = (const float*)d_in[2];
    float* out = (float*)d_out;

    dim3 grid(64, 16);   // 8x8 pixel tiles of 16x16, 16 batches
    rbf_deform_kernel<<<grid, TPB>>>(betas, alphas, kern, out);
}

// round 2
// speedup vs baseline: 1.3444x; 1.3444x over previous
#include <cuda_runtime.h>
#include <cuda_bf16.h>

// KBpA: fused sparse-grid deformation (separable 21x21 gaussian conv) +
// truncated separable RBF kmat @ alphas.  B=16, H=W=128, 32x32 centers.
//
// Per 4-pixel quad: out_p = sum_k ex_p[k] * (A[im-6+k, j0..j0+15] . ey_p)
// with 13 rows x 16 cols window (guaranteed >= +-5 cells per pixel).

#define TPB 64
#define KCC 0.52729242f   // exp(-0.64)

static __device__ __forceinline__ unsigned long long pk2(float lo, float hi) {
    unsigned long long r;
    asm("mov.b64 %0, {%1, %2};" : "=l"(r) : "f"(lo), "f"(hi));
    return r;
}
static __device__ __forceinline__ float2 unpk2(unsigned long long v) {
    float2 r;
    asm("mov.b64 {%0, %1}, %2;" : "=f"(r.x), "=f"(r.y) : "l"(v));
    return r;
}
static __device__ __forceinline__ void fma2(unsigned long long& d,
                                            unsigned long long a,
                                            unsigned long long b) {
    asm("fma.rn.f32x2 %0, %1, %2, %0;" : "+l"(d) : "l"(a), "l"(b));
}

__global__ __launch_bounds__(TPB, 8) void rbf_deform_kernel(
    const float* __restrict__ betas,   // (16, 1024, 2)
    const float* __restrict__ alphas,  // (1024,)
    const float* __restrict__ kern,    // (21, 21)  (separable: g g^T)
    float* __restrict__ out)           // (16, 16384)
{
    __shared__ __align__(16) float sA[24 * 32];     // local alphas window
    __shared__ float sB[2][10][12];                 // local betas window
    __shared__ __align__(16) float sT[2][10][16];   // deformation col-pass
    __shared__ float sG[4][8];                      // 1D conv taps per phase

    const int b  = blockIdx.y;
    const int r0 = (blockIdx.x >> 3) << 4;
    const int c0 = (blockIdx.x & 7)  << 4;
    const int tid = threadIdx.x;

    const int ribase = (r0 >> 2) - 10;   // sA row 0 = alphas row ribase
    const int cjbase = (c0 >> 2) - 12;   // sA col 0 = alphas col cjbase
    const int gibase = (r0 >> 2) - 2;
    const int gjbase = (c0 >> 2) - 2;

    // ---- cooperative fills (zero padding absorbs all boundaries) ----
    for (int idx = tid; idx < 24 * 32; idx += TPB) {
        const int i = ribase + (idx >> 5), j = cjbase + (idx & 31);
        float v = 0.f;
        if ((unsigned)i < 32u && (unsigned)j < 32u) v = alphas[(i << 5) + j];
        sA[idx] = v;
    }
    for (int idx = tid; idx < 100; idx += TPB) {
        const int rl = idx / 10, clc = idx - rl * 10;
        const int gi = gibase + rl, gj = gjbase + clc;
        float v0 = 0.f, v1 = 0.f;
        if ((unsigned)gi < 32u && (unsigned)gj < 32u) {
            const int m = (((b << 5) + gi) << 5) + gj;
            v0 = betas[2 * m];
            v1 = betas[2 * m + 1];
        }
        sB[0][rl][clc] = v0;
        sB[1][rl][clc] = v1;
    }
    if (tid < 24) {
        const int s = tid / 6, k = tid - s * 6;
        const int dc0 = (s == 3) ? 7 : (8 + s);
        const int dc = dc0 - 4 * k;
        // 1D factor: kern[u][10] == exp(-ax_u^2/18)  (kern[10][10] == 1)
        sG[s][k] = (dc >= -10 && dc <= 10) ? kern[(dc + 10) * 21 + 10] : 0.f;
    }
    __syncthreads();

    // ---- deformation column pass: T[ch][gi][c] = sum_l g_c[l] B[gi, gj0(c)+l]
    for (int idx = tid; idx < 160; idx += TPB) {
        const int giloc = idx >> 4, cloc = idx & 15;
        const int c = c0 + cloc;
        const int s = c & 3;
        const int gjl = (c >> 2) - (c0 >> 2) + (s == 3);
        float t0 = 0.f, t1 = 0.f;
#pragma unroll
        for (int l = 0; l < 6; ++l) {
            const float w = sG[s][l];
            t0 = fmaf(w, sB[0][giloc][gjl + l], t0);
            t1 = fmaf(w, sB[1][giloc][gjl + l], t1);
        }
        sT[0][giloc][cloc] = t0;
        sT[1][giloc][cloc] = t1;
    }
    __syncthreads();

    // ---- per-thread quad: 4 consecutive pixels along c ----
    const int rr = r0 + (tid >> 2);
    const int cb = c0 + ((tid & 3) << 2);
    const int sr = rr & 3;
    const int g0 = (rr >> 2) - (r0 >> 2) + (sr == 3);
    const int cl = cb - c0;

    // deformation row pass (6 taps), 4 pixels at once via float4 T loads
    float4 d0 = make_float4(0.f, 0.f, 0.f, 0.f), d1 = d0;
#pragma unroll
    for (int k = 0; k < 6; ++k) {
        const float w = sG[sr][k];
        const float4 t0 = *(const float4*)&sT[0][g0 + k][cl];
        const float4 t1 = *(const float4*)&sT[1][g0 + k][cl];
        d0.x = fmaf(w, t0.x, d0.x); d0.y = fmaf(w, t0.y, d0.y);
        d0.z = fmaf(w, t0.z, d0.z); d0.w = fmaf(w, t0.w, d0.w);
        d1.x = fmaf(w, t1.x, d1.x); d1.y = fmaf(w, t1.y, d1.y);
        d1.z = fmaf(w, t1.z, d1.z); d1.w = fmaf(w, t1.w, d1.w);
    }
    const float xs0 = (float)rr - d0.x, xs1 = (float)rr - d0.y;
    const float xs2 = (float)rr - d0.z, xs3 = (float)rr - d0.w;
    const float ys0 = (float)(cb)     - d1.x, ys1 = (float)(cb + 1) - d1.y;
    const float ys2 = (float)(cb + 2) - d1.z, ys3 = (float)(cb + 3) - d1.w;

    const float xav = (xs0 + xs1 + xs2 + xs3) * 0.25f;
    const float yav = (ys0 + ys1 + ys2 + ys3) * 0.25f;
    const int im = __float2int_rn((xav - 2.f) * 0.25f);
    const int jm = __float2int_rn((yav - 2.f) * 0.25f);
    const int j0 = (jm - 6) & ~3;               // 4-aligned window start

    // ey[16] per pixel via exp-ratio chain, packed to f32x2 pairs
    unsigned long long eyp[4][8];
    float ee[4], er[4], acc[4];
    const float xsv[4] = {xs0, xs1, xs2, xs3};
    const float ysv[4] = {ys0, ys1, ys2, ys3};
#pragma unroll
    for (int p = 0; p < 4; ++p) {
        const float dy = ysv[p] - (float)(4 * j0 + 2);
        float e  = __expf(dy * dy * -0.02f);
        float rh = __expf(0.16f * dy - 0.32f);
        float ev[16];
        ev[0] = e;
#pragma unroll
        for (int l = 1; l < 16; ++l) { e *= rh; rh *= KCC; ev[l] = e; }
#pragma unroll
        for (int l = 0; l < 8; ++l) eyp[p][l] = pk2(ev[2 * l], ev[2 * l + 1]);

        const float dx = xsv[p] - (float)(4 * (im - 6) + 2);
        ee[p]  = __expf(dx * dx * -0.02f);
        er[p]  = __expf(0.16f * dx - 0.32f);
        acc[p] = 0.f;
    }

    // main: 13 A rows shared by the quad; packed f32x2 dot16 per pixel
    const float* Arow = &sA[(im - 6 - ribase) * 32 + (j0 - cjbase)];
#pragma unroll
    for (int k = 0; k < 13; ++k) {
        const ulonglong2 A0 = *(const ulonglong2*)(Arow);
        const ulonglong2 A1 = *(const ulonglong2*)(Arow + 4);
        const ulonglong2 A2 = *(const ulonglong2*)(Arow + 8);
        const ulonglong2 A3 = *(const ulonglong2*)(Arow + 12);
#pragma unroll
        for (int p = 0; p < 4; ++p) {
            unsigned long long s2 = 0ull;
            fma2(s2, A0.x, eyp[p][0]); fma2(s2, A0.y, eyp[p][1]);
            fma2(s2, A1.x, eyp[p][2]); fma2(s2, A1.y, eyp[p][3]);
            fma2(s2, A2.x, eyp[p][4]); fma2(s2, A2.y, eyp[p][5]);
            fma2(s2, A3.x, eyp[p][6]); fma2(s2, A3.y, eyp[p][7]);
            const float2 sv = unpk2(s2);
            acc[p] = fmaf(ee[p], sv.x + sv.y, acc[p]);
            ee[p] *= er[p];
            er[p] *= KCC;
        }
        Arow += 32;
    }

    *(float4*)&out[(b << 14) + (rr << 7) + cb] =
        make_float4(acc[0], acc[1], acc[2], acc[3]);
}

extern "C" void kernel_launch(void* const* d_in, const int* in_sizes, int n_in,
                              void* d_out, int out_size) {
    const float* betas  = (const float*)d_in[0];
    const float* alphas = (const float*)d_in[1];
    const float* kern   = (const float*)d_in[2];
    float* out = (float*)d_out;

    dim3 grid(64, 16);   // 8x8 tiles of 16x16 pixels, 16 batches
    rbf_deform_kernel<<<grid, TPB>>>(betas, alphas, kern, out);
}